// round 4
// baseline (speedup 1.0000x reference)
#include <cuda_runtime.h>
#include <cstdint>

#define B_ 256
#define T_ 512
#define R_ 2048
#define O_ 10

#define CHUNK 4096                 // floats in one 64x64 operand chunk (fragment order)
#define STAGE (2*CHUNK)            // A chunk + B chunk
#define NSTAGE 3
#define SMEM_BYTES (NSTAGE*STAGE*4)

// ---------------- device scratch ----------------
__device__ __align__(128) float g_H[2][B_ * R_];               // fp32 state
__device__ __align__(128) float g_Htf[2][4 * 32 * CHUNK];      // tf32 A operand, fragment order
__device__ __align__(128) float g_Xtf[T_ * 4 * CHUNK];         // tf32 x chunks, fragment order
__device__ __align__(128) float g_Wtf[32 * 33 * CHUNK];        // tf32 B operand, fragment order

__device__ __forceinline__ uint32_t f2tf(float f) {
    uint32_t u; asm("cvt.rna.tf32.f32 %0, %1;" : "=r"(u) : "f"(f)); return u;
}
__device__ __forceinline__ void cp16(void* dst, const void* src) {
    uint32_t d = (uint32_t)__cvta_generic_to_shared(dst);
    asm volatile("cp.async.cg.shared.global [%0], [%1], 16;\n" :: "r"(d), "l"(src));
}

#define MMA(cc, av, bb0, bb1) \
    asm volatile("mma.sync.aligned.m16n8k8.row.col.f32.tf32.tf32.f32 " \
        "{%0,%1,%2,%3},{%4,%5,%6,%7},{%8,%9},{%0,%1,%2,%3};\n" \
        : "+f"((cc)[0]), "+f"((cc)[1]), "+f"((cc)[2]), "+f"((cc)[3]) \
        : "r"((av).x), "r"((av).y), "r"((av).z), "r"((av).w), "r"(bb0), "r"(bb1))

// ---------------- prep: permute + tf32-round operands once ----------------
// Fragment layout per 64x64 chunk: [k8 0..7][half 0..1][lane 0..31][8 floats]
// A lane floats: v = mi*4 + (rhi + 2*khalf); element (m = half*32+mi*16+rhi*8+g, k = k8*8+khalf*4+tg)
// B lane floats: v = ni*2 + r;               element (k = k8*8+r*4+tg,        n = half*32+ni*8+g)
__global__ void prep_W(const float* __restrict__ Wres, const float* __restrict__ Win) {
    uint32_t idx = blockIdx.x * 256u + threadIdx.x;      // 2112*2048
    uint32_t k = idx >> 11, n = idx & 2047u;
    float v = (k < 2048u) ? Wres[(size_t)k * R_ + n] : Win[(size_t)(k - 2048u) * R_ + n];
    uint32_t kc = k >> 6, kl = k & 63u;
    uint32_t k8 = kl >> 3, r = (kl >> 2) & 1u, tg = kl & 3u;
    uint32_t bn = n >> 6, nh = (n >> 5) & 1u, ni = (n >> 3) & 3u, g = n & 7u;
    g_Wtf[(bn * 33u + kc) * CHUNK + k8 * 512u + nh * 256u + (g * 4u + tg) * 8u + ni * 2u + r]
        = __uint_as_float(f2tf(v));
}

__global__ void prep_X(const float* __restrict__ x) {
    uint32_t idx = blockIdx.x * 256u + threadIdx.x;      // 256*512*64
    uint32_t b = idx >> 15, t = (idx >> 6) & 511u, i = idx & 63u;
    float v = x[idx];
    uint32_t bm = b >> 6, mh = (b >> 5) & 1u, mi = (b >> 4) & 1u, rhi = (b >> 3) & 1u, g = b & 7u;
    uint32_t k8 = i >> 3, khalf = (i >> 2) & 1u, tg = i & 3u;
    g_Xtf[(t * 4u + bm) * CHUNK + k8 * 512u + mh * 256u + (g * 4u + tg) * 8u + mi * 4u + rhi + 2u * khalf]
        = __uint_as_float(f2tf(v));
}

__global__ void esn_zero() {
    uint32_t i = blockIdx.x * 256u + threadIdx.x;        // 131072 float4 each
    ((float4*)g_H[0])[i]   = make_float4(0.f, 0.f, 0.f, 0.f);
    ((float4*)g_Htf[0])[i] = make_float4(0.f, 0.f, 0.f, 0.f);
}

// ---------------- step: H_new = 0.5H + 0.5 tanh([H|x_t] @ Wcat) ----------------
// 256 threads, 8 warps in 2x4: warp tile 32(M) x 16(N).
__global__ __launch_bounds__(256, 1) void esn_step(int t)
{
    extern __shared__ float sm[];
    const int tid = threadIdx.x, warp = tid >> 5, lane = tid & 31;
    const int wm = warp & 1, wn = warp >> 1;          // wm: 0-1, wn: 0-3
    const int g = lane >> 2, tg = lane & 3;
    const int bn = blockIdx.x, bm = blockIdx.y;
    const int cur = t & 1, nxt = cur ^ 1;

    const float* __restrict__ aBase = g_Htf[cur] + (size_t)bm * 32 * CHUNK;
    const float* __restrict__ xSrc  = g_Xtf + (size_t)(t * 4 + bm) * CHUNK;
    const float* __restrict__ bBase = g_Wtf + (size_t)bn * 33 * CHUNK;

    float c[2][2][4];
#pragma unroll
    for (int mi = 0; mi < 2; mi++)
#pragma unroll
        for (int ni = 0; ni < 2; ni++)
#pragma unroll
            for (int i = 0; i < 4; i++) c[mi][ni][i] = 0.f;

    auto issue = [&](int kc) {
        float* dst = sm + (kc % 3) * STAGE;
        const float* a = (kc < 32) ? (aBase + (size_t)kc * CHUNK) : xSrc;
        const float* b = bBase + (size_t)kc * CHUNK;
#pragma unroll
        for (int it = 0; it < 4; it++) { int e = (it * 256 + tid) * 4; cp16(dst + e, a + e); }
#pragma unroll
        for (int it = 0; it < 4; it++) { int e = (it * 256 + tid) * 4; cp16(dst + CHUNK + e, b + e); }
        asm volatile("cp.async.commit_group;\n" ::);
    };

    issue(0);
    issue(1);

    for (int kc = 0; kc < 33; kc++) {
        if (kc < 32) asm volatile("cp.async.wait_group 1;\n" ::);
        else         asm volatile("cp.async.wait_group 0;\n" ::);
        __syncthreads();
        if (kc + 2 < 33) issue(kc + 2);

        // A fragments: warp's m-half; two uint4 per k8 (mi=0 in [0], mi=1 in [1])
        const uint4* pA = (const uint4*)(sm + (kc % 3) * STAGE + wm * 256) + lane * 2;
        // B fragment: warp's 16 cols = single uint4 per k8
        const uint4* pB = (const uint4*)(sm + (kc % 3) * STAGE + CHUNK + (wn >> 1) * 256)
                          + lane * 2 + (wn & 1);

        uint4 fa[2][2], fb[2];
        fa[0][0] = pA[0]; fa[0][1] = pA[1];
        fb[0] = pB[0];
#pragma unroll
        for (int k8 = 0; k8 < 8; k8++) {
            const int cb = k8 & 1, nb = cb ^ 1;
            if (k8 < 7) {
                fa[nb][0] = pA[(k8 + 1) * 128];
                fa[nb][1] = pA[(k8 + 1) * 128 + 1];
                fb[nb]    = pB[(k8 + 1) * 128];
            }
            MMA(c[0][0], fa[cb][0], fb[cb].x, fb[cb].y);
            MMA(c[0][1], fa[cb][0], fb[cb].z, fb[cb].w);
            MMA(c[1][0], fa[cb][1], fb[cb].x, fb[cb].y);
            MMA(c[1][1], fa[cb][1], fb[cb].z, fb[cb].w);
        }
    }

    // ---------------- epilogue: leak + tanh, write H fp32 + H tf32(fragment order) ----------------
#pragma unroll
    for (int mi = 0; mi < 2; mi++) {
#pragma unroll
        for (int ni = 0; ni < 2; ni++) {
            const int baserow = bm * 64 + wm * 32 + mi * 16 + g;
            const int c64 = wn * 16 + ni * 8 + tg * 2;
            const int col = bn * 64 + c64;
#pragma unroll
            for (int rhi = 0; rhi < 2; rhi++) {
                const int row = baserow + rhi * 8;
                const float2 ho = *(const float2*)(g_H[cur] + (size_t)row * R_ + col);
                float h0 = 0.5f * ho.x + 0.5f * tanhf(c[mi][ni][2 * rhi]);
                float h1 = 0.5f * ho.y + 0.5f * tanhf(c[mi][ni][2 * rhi + 1]);
                *(float2*)(g_H[nxt] + (size_t)row * R_ + col) = make_float2(h0, h1);
#pragma unroll
                for (int q = 0; q < 2; q++) {
                    const int cc = c64 + q;
                    const int k8p = cc >> 3, tgp = cc & 3, khp = (cc >> 2) & 1;
                    const uint32_t off = (uint32_t)(bm * 32 + bn) * CHUNK + k8p * 512
                        + wm * 256 + (g * 4 + tgp) * 8 + mi * 4 + rhi + 2 * khp;
                    g_Htf[nxt][off] = __uint_as_float(f2tf(q ? h1 : h0));
                }
            }
        }
    }
}

// ---------------- readout ----------------
__global__ void esn_readout(const float* __restrict__ W_out,
                            const float* __restrict__ b_out,
                            float* __restrict__ out)
{
    int b = blockIdx.x, tid = threadIdx.x;
    const float* h = g_H[0] + (size_t)b * R_;
    float acc[O_];
#pragma unroll
    for (int o = 0; o < O_; o++) acc[o] = 0.f;
    for (int r = tid; r < R_; r += 256) {
        float hv = h[r];
#pragma unroll
        for (int o = 0; o < O_; o++) acc[o] += hv * W_out[r * O_ + o];
    }
#pragma unroll
    for (int o = 0; o < O_; o++)
#pragma unroll
        for (int off = 16; off > 0; off >>= 1)
            acc[o] += __shfl_down_sync(0xffffffffu, acc[o], off);
    __shared__ float s[8][O_];
    if ((tid & 31) == 0)
#pragma unroll
        for (int o = 0; o < O_; o++) s[tid >> 5][o] = acc[o];
    __syncthreads();
    if (tid < O_) {
        float v = b_out[tid];
#pragma unroll
        for (int w = 0; w < 8; w++) v += s[w][tid];
        out[b * O_ + tid] = v;
    }
}

extern "C" void kernel_launch(void* const* d_in, const int* in_sizes, int n_in,
                              void* d_out, int out_size)
{
    const float* x     = (const float*)d_in[0];
    const float* W_in  = (const float*)d_in[1];
    const float* W_res = (const float*)d_in[2];
    const float* W_out = (const float*)d_in[3];
    const float* b_out = (const float*)d_in[4];
    float* out = (float*)d_out;

    cudaFuncSetAttribute(esn_step, cudaFuncAttributeMaxDynamicSharedMemorySize, SMEM_BYTES);

    prep_W<<<(2112 * 2048) / 256, 256>>>(W_res, W_in);
    prep_X<<<(B_ * T_ * 64) / 256, 256>>>(x);
    esn_zero<<<512, 256>>>();

    dim3 grid(32, 4);   // bn x bm = 128 CTAs
    for (int t = 0; t < T_; t++)
        esn_step<<<grid, 256, SMEM_BYTES>>>(t);

    esn_readout<<<B_, 256>>>(W_out, b_out, out);
}

// round 5
// speedup vs baseline: 2.2905x; 2.2905x over previous
#include <cuda_runtime.h>
#include <cuda_fp16.h>
#include <cstdint>

#define B_ 256
#define T_ 512
#define R_ 2048
#define O_ 10

#define CHUNK_B 8192               // bytes of one 64x64 fp16 operand chunk (fragment order)
#define STAGE_B (2*CHUNK_B)        // A + B
#define NSTAGE 4
#define SMEM_BYTES (NSTAGE*STAGE_B)

// ---------------- device scratch ----------------
__device__ __align__(128) float    g_H[2][B_ * R_];              // fp32 state
__device__ __align__(128) uint32_t g_Hh[2][4 * 32 * 2048];       // fp16 A operand, fragment order
__device__ __align__(128) uint32_t g_Xh[T_ * 4 * 2048];          // fp16 x chunks, fragment order
__device__ __align__(128) uint32_t g_Wh[32 * 33 * 2048];         // fp16 B operand, fragment order

__device__ __forceinline__ void cp16(void* dst, const void* src) {
    uint32_t d = (uint32_t)__cvta_generic_to_shared(dst);
    asm volatile("cp.async.cg.shared.global [%0], [%1], 16;\n" :: "r"(d), "l"(src));
}

#define MMA(cc, av, bb0, bb1) \
    asm volatile("mma.sync.aligned.m16n8k16.row.col.f32.f16.f16.f32 " \
        "{%0,%1,%2,%3},{%4,%5,%6,%7},{%8,%9},{%0,%1,%2,%3};\n" \
        : "+f"((cc)[0]), "+f"((cc)[1]), "+f"((cc)[2]), "+f"((cc)[3]) \
        : "r"((av).x), "r"((av).y), "r"((av).z), "r"((av).w), "r"(bb0), "r"(bb1))

// ---------------- prep: permute + fp16-round operands once ----------------
// A chunk (64m x 64k), u32 units: ((k16*4 + mh*2 + mi)*32 + lane)*4 + (rhi + 2*khalf), halves by kodd
//   where m = mh*32+mi*16+rhi*8+g, k = k16*16+khalf*8+tg*2+kodd, lane = g*4+tg
// B chunk (64k x 64n), u32 units: ((k16*2 + nh)*32 + lane)*8 + (ni>>1)*4 + (ni&1)*2 + khalf, halves by kodd
//   where n = nh*32+ni*8+g, k as above
__global__ void prep_W(const float* __restrict__ Wres, const float* __restrict__ Win) {
    uint32_t idx = blockIdx.x * 256u + threadIdx.x;      // 1056*2048 k-pairs
    uint32_t k2 = idx >> 11, n = idx & 2047u;
    uint32_t k = k2 * 2u;
    float v0, v1;
    if (k < 2048u) { v0 = Wres[(size_t)k * R_ + n]; v1 = Wres[(size_t)(k + 1) * R_ + n]; }
    else           { v0 = Win[(size_t)(k - 2048u) * R_ + n]; v1 = Win[(size_t)(k - 2047u) * R_ + n]; }
    uint32_t kc = k >> 6, kl = k & 63u;
    uint32_t k16 = kl >> 4, kin = kl & 15u, khalf = kin >> 3, tg = (kin & 7u) >> 1;
    uint32_t g = n & 7u, ni = (n >> 3) & 3u, nh = (n >> 5) & 1u, bn = n >> 6;
    uint32_t lane = g * 4u + tg;
    __half2 h = __floats2half2_rn(v0, v1);
    g_Wh[(bn * 33u + kc) * 2048u + ((k16 * 2u + nh) * 32u + lane) * 8u
         + (ni >> 1) * 4u + (ni & 1u) * 2u + khalf] = *(uint32_t*)&h;
}

__global__ void prep_X(const float* __restrict__ x) {
    uint32_t idx = blockIdx.x * 256u + threadIdx.x;      // 256*512*32 i-pairs
    uint32_t b = idx >> 14, t = (idx >> 5) & 511u, i = (idx & 31u) * 2u;
    float2 v = *(const float2*)(x + ((size_t)b * T_ + t) * 64u + i);
    uint32_t k16 = i >> 4, kin = i & 15u, khalf = kin >> 3, tg = (kin & 7u) >> 1;
    uint32_t g = b & 7u, rhi = (b >> 3) & 1u, mi = (b >> 4) & 1u, mh = (b >> 5) & 1u, bm = b >> 6;
    uint32_t lane = g * 4u + tg;
    __half2 h = __floats2half2_rn(v.x, v.y);
    g_Xh[(t * 4u + bm) * 2048u + ((k16 * 4u + mh * 2u + mi) * 32u + lane) * 4u
         + rhi + 2u * khalf] = *(uint32_t*)&h;
}

__global__ void esn_zero() {
    uint32_t i = blockIdx.x * 256u + threadIdx.x;        // 131072
    ((float4*)g_H[0])[i] = make_float4(0.f, 0.f, 0.f, 0.f);
    if (i < 65536u) ((uint4*)g_Hh[0])[i] = make_uint4(0u, 0u, 0u, 0u);
}

// ---------------- step: H_new = 0.5H + 0.5 tanh([H|x_t] @ Wcat) ----------------
// 128 threads, 4 warps in 2x2, warp tile 32(M) x 32(N), fp16 m16n8k16.
__global__ __launch_bounds__(128, 1) void esn_step(int t)
{
    extern __shared__ char smem[];
    const int tid = threadIdx.x, warp = tid >> 5, lane = tid & 31;
    const int wm = warp & 1, wn = warp >> 1;
    const int g = lane >> 2, tg = lane & 3;
    const int bn = blockIdx.x, bm = blockIdx.y;
    const int cur = t & 1, nxt = cur ^ 1;

    float c[2][4][4];
#pragma unroll
    for (int mi = 0; mi < 2; mi++)
#pragma unroll
        for (int nq = 0; nq < 4; nq++)
#pragma unroll
            for (int i = 0; i < 4; i++) c[mi][nq][i] = 0.f;

    auto issue = [&](int kc) {
        char* dst = smem + (kc & 3) * STAGE_B;
        const char* a = (kc < 32)
            ? (const char*)(g_Hh[cur] + (size_t)(bm * 32 + kc) * 2048)
            : (const char*)(g_Xh + (size_t)(t * 4 + bm) * 2048);
        const char* b = (const char*)(g_Wh + (size_t)(bn * 33 + kc) * 2048);
#pragma unroll
        for (int it = 0; it < 4; it++) { int e = (it * 128 + tid) * 16; cp16(dst + e, a + e); }
#pragma unroll
        for (int it = 0; it < 4; it++) { int e = (it * 128 + tid) * 16; cp16(dst + CHUNK_B + e, b + e); }
        asm volatile("cp.async.commit_group;\n" ::);
    };

    issue(0); issue(1); issue(2);

    for (int kc = 0; kc < 33; kc++) {
        if (kc < 30) asm volatile("cp.async.wait_group 2;\n" ::);
        else if (kc < 31) asm volatile("cp.async.wait_group 1;\n" ::);
        else asm volatile("cp.async.wait_group 0;\n" ::);
        __syncthreads();
        if (kc + 3 < 33) issue(kc + 3);

        const uint4* sA = (const uint4*)(smem + (kc & 3) * STAGE_B);
        const uint4* sB = (const uint4*)(smem + (kc & 3) * STAGE_B + CHUNK_B);
        // per k16: A uint4 at (k16*4 + wm*2 + mi)*32 + lane ; B 2x uint4 at (k16*2+wn)*64 + lane*2
        uint4 fa[2][2], fb[2][2];
        fa[0][0] = sA[(wm * 2 + 0) * 32 + lane];
        fa[0][1] = sA[(wm * 2 + 1) * 32 + lane];
        fb[0][0] = sB[wn * 64 + lane * 2];
        fb[0][1] = sB[wn * 64 + lane * 2 + 1];
#pragma unroll
        for (int k16 = 0; k16 < 4; k16++) {
            const int cb = k16 & 1, nb = cb ^ 1;
            if (k16 < 3) {
                fa[nb][0] = sA[((k16 + 1) * 4 + wm * 2 + 0) * 32 + lane];
                fa[nb][1] = sA[((k16 + 1) * 4 + wm * 2 + 1) * 32 + lane];
                fb[nb][0] = sB[((k16 + 1) * 2 + wn) * 64 + lane * 2];
                fb[nb][1] = sB[((k16 + 1) * 2 + wn) * 64 + lane * 2 + 1];
            }
            MMA(c[0][0], fa[cb][0], fb[cb][0].x, fb[cb][0].y);
            MMA(c[0][1], fa[cb][0], fb[cb][0].z, fb[cb][0].w);
            MMA(c[0][2], fa[cb][0], fb[cb][1].x, fb[cb][1].y);
            MMA(c[0][3], fa[cb][0], fb[cb][1].z, fb[cb][1].w);
            MMA(c[1][0], fa[cb][1], fb[cb][0].x, fb[cb][0].y);
            MMA(c[1][1], fa[cb][1], fb[cb][0].z, fb[cb][0].w);
            MMA(c[1][2], fa[cb][1], fb[cb][1].x, fb[cb][1].y);
            MMA(c[1][3], fa[cb][1], fb[cb][1].z, fb[cb][1].w);
        }
    }

    // ---------------- epilogue: leak + tanh, write H fp32 + H fp16(fragment order) ----------------
#pragma unroll
    for (int mi = 0; mi < 2; mi++) {
#pragma unroll
        for (int nq = 0; nq < 4; nq++) {
            const int col = bn * 64 + wn * 32 + nq * 8 + tg * 2;
#pragma unroll
            for (int rhi = 0; rhi < 2; rhi++) {
                const int row = bm * 64 + wm * 32 + mi * 16 + rhi * 8 + g;
                const float2 ho = *(const float2*)(g_H[cur] + (size_t)row * R_ + col);
                float h0 = 0.5f * ho.x + 0.5f * tanhf(c[mi][nq][2 * rhi]);
                float h1 = 0.5f * ho.y + 0.5f * tanhf(c[mi][nq][2 * rhi + 1]);
                *(float2*)(g_H[nxt] + (size_t)row * R_ + col) = make_float2(h0, h1);
                __half2 hh = __floats2half2_rn(h0, h1);
                const uint32_t off = (uint32_t)(bm * 32 + bn) * 2048u
                    + (uint32_t)((wn * 2 + (nq >> 1)) * 4 + wm * 2 + mi) * 128u
                    + (uint32_t)lane * 4u + (uint32_t)(rhi + 2 * (nq & 1));
                g_Hh[nxt][off] = *(uint32_t*)&hh;
            }
        }
    }
}

// ---------------- readout ----------------
__global__ void esn_readout(const float* __restrict__ W_out,
                            const float* __restrict__ b_out,
                            float* __restrict__ out)
{
    int b = blockIdx.x, tid = threadIdx.x;
    const float* h = g_H[0] + (size_t)b * R_;
    float acc[O_];
#pragma unroll
    for (int o = 0; o < O_; o++) acc[o] = 0.f;
    for (int r = tid; r < R_; r += 256) {
        float hv = h[r];
#pragma unroll
        for (int o = 0; o < O_; o++) acc[o] += hv * W_out[r * O_ + o];
    }
#pragma unroll
    for (int o = 0; o < O_; o++)
#pragma unroll
        for (int off = 16; off > 0; off >>= 1)
            acc[o] += __shfl_down_sync(0xffffffffu, acc[o], off);
    __shared__ float s[8][O_];
    if ((tid & 31) == 0)
#pragma unroll
        for (int o = 0; o < O_; o++) s[tid >> 5][o] = acc[o];
    __syncthreads();
    if (tid < O_) {
        float v = b_out[tid];
#pragma unroll
        for (int w = 0; w < 8; w++) v += s[w][tid];
        out[b * O_ + tid] = v;
    }
}

extern "C" void kernel_launch(void* const* d_in, const int* in_sizes, int n_in,
                              void* d_out, int out_size)
{
    const float* x     = (const float*)d_in[0];
    const float* W_in  = (const float*)d_in[1];
    const float* W_res = (const float*)d_in[2];
    const float* W_out = (const float*)d_in[3];
    const float* b_out = (const float*)d_in[4];
    float* out = (float*)d_out;

    cudaFuncSetAttribute(esn_step, cudaFuncAttributeMaxDynamicSharedMemorySize, SMEM_BYTES);

    prep_W<<<(1056 * 2048) / 256, 256>>>(W_res, W_in);
    prep_X<<<(B_ * T_ * 32) / 256, 256>>>(x);
    esn_zero<<<512, 256>>>();

    dim3 grid(32, 4);   // bn x bm = 128 CTAs
    for (int t = 0; t < T_; t++)
        esn_step<<<grid, 128, SMEM_BYTES>>>(t);

    esn_readout<<<B_, 256>>>(W_out, b_out, out);
}

// round 6
// speedup vs baseline: 2.7312x; 1.1924x over previous
#include <cuda_runtime.h>
#include <cuda_fp16.h>
#include <cstdint>

#define B_ 256
#define T_ 512
#define R_ 2048
#define O_ 10

#define CHUNK_B 8192               // bytes of one 64x64 fp16 operand chunk (fragment order)
#define STAGE_B (2*CHUNK_B)        // A + B = 16 KB
#define SMEM_BYTES (6*STAGE_B)     // 3 stages per warp-group x 2 groups = 96 KB

// ---------------- device scratch ----------------
__device__ __align__(128) float    g_H[2][B_ * R_];              // fp32 state
__device__ __align__(128) uint32_t g_Hh[2][4 * 32 * 2048];       // fp16 A operand, fragment order
__device__ __align__(128) uint32_t g_Xh[T_ * 4 * 2048];          // fp16 x chunks, fragment order
__device__ __align__(128) uint32_t g_Wh[32 * 33 * 2048];         // fp16 B operand, fragment order

__device__ __forceinline__ void cp16(void* dst, const void* src) {
    uint32_t d = (uint32_t)__cvta_generic_to_shared(dst);
    asm volatile("cp.async.cg.shared.global [%0], [%1], 16;\n" :: "r"(d), "l"(src));
}

#define MMA(cc, av, bb0, bb1) \
    asm volatile("mma.sync.aligned.m16n8k16.row.col.f32.f16.f16.f32 " \
        "{%0,%1,%2,%3},{%4,%5,%6,%7},{%8,%9},{%0,%1,%2,%3};\n" \
        : "+f"((cc)[0]), "+f"((cc)[1]), "+f"((cc)[2]), "+f"((cc)[3]) \
        : "r"((av).x), "r"((av).y), "r"((av).z), "r"((av).w), "r"(bb0), "r"(bb1))

// ---------------- prep: permute + fp16-round operands once ----------------
__global__ void prep_W(const float* __restrict__ Wres, const float* __restrict__ Win) {
    uint32_t idx = blockIdx.x * 256u + threadIdx.x;      // 1056*2048 k-pairs
    uint32_t k2 = idx >> 11, n = idx & 2047u;
    uint32_t k = k2 * 2u;
    float v0, v1;
    if (k < 2048u) { v0 = Wres[(size_t)k * R_ + n]; v1 = Wres[(size_t)(k + 1) * R_ + n]; }
    else           { v0 = Win[(size_t)(k - 2048u) * R_ + n]; v1 = Win[(size_t)(k - 2047u) * R_ + n]; }
    uint32_t kc = k >> 6, kl = k & 63u;
    uint32_t k16 = kl >> 4, kin = kl & 15u, khalf = kin >> 3, tg = (kin & 7u) >> 1;
    uint32_t g = n & 7u, ni = (n >> 3) & 3u, nh = (n >> 5) & 1u, bn = n >> 6;
    uint32_t lane = g * 4u + tg;
    __half2 h = __floats2half2_rn(v0, v1);
    g_Wh[(bn * 33u + kc) * 2048u + ((k16 * 2u + nh) * 32u + lane) * 8u
         + (ni >> 1) * 4u + (ni & 1u) * 2u + khalf] = *(uint32_t*)&h;
}

__global__ void prep_X(const float* __restrict__ x) {
    uint32_t idx = blockIdx.x * 256u + threadIdx.x;      // 256*512*32 i-pairs
    uint32_t b = idx >> 14, t = (idx >> 5) & 511u, i = (idx & 31u) * 2u;
    float2 v = *(const float2*)(x + ((size_t)b * T_ + t) * 64u + i);
    uint32_t k16 = i >> 4, kin = i & 15u, khalf = kin >> 3, tg = (kin & 7u) >> 1;
    uint32_t g = b & 7u, rhi = (b >> 3) & 1u, mi = (b >> 4) & 1u, mh = (b >> 5) & 1u, bm = b >> 6;
    uint32_t lane = g * 4u + tg;
    __half2 h = __floats2half2_rn(v.x, v.y);
    g_Xh[(t * 4u + bm) * 2048u + ((k16 * 4u + mh * 2u + mi) * 32u + lane) * 4u
         + rhi + 2u * khalf] = *(uint32_t*)&h;
}

__global__ void esn_zero() {
    uint32_t i = blockIdx.x * 256u + threadIdx.x;        // 131072
    ((float4*)g_H[0])[i] = make_float4(0.f, 0.f, 0.f, 0.f);
    if (i < 65536u) ((uint4*)g_Hh[0])[i] = make_uint4(0u, 0u, 0u, 0u);
}

// ---------------- step: H_new = 0.5H + 0.5 tanh([H|x_t] @ Wcat) ----------------
// 256 threads = 2 warp-groups of 4 warps. Each group: independent split-K stream
// (group 0: even chunks + x; group 1: odd chunks), own 3-stage pipeline + named barrier.
__global__ __launch_bounds__(256, 1) void esn_step(int t)
{
    extern __shared__ char smem[];
    const int tid = threadIdx.x;
    const int gid = tid >> 7, gtid = tid & 127;
    const int warp = gtid >> 5, lane = gtid & 31;
    const int wm = warp & 1, wn = warp >> 1;
    const int g = lane >> 2, tg = lane & 3;
    const int bn = blockIdx.x, bm = blockIdx.y;
    const int cur = t & 1, nxt = cur ^ 1;
    char* gsm = smem + gid * 3 * STAGE_B;
    const int NCH = 17 - gid;            // group 0: 17 chunks, group 1: 16

    __align__(16) float c[2][4][4];
#pragma unroll
    for (int mi = 0; mi < 2; mi++)
#pragma unroll
        for (int nq = 0; nq < 4; nq++)
#pragma unroll
            for (int i = 0; i < 4; i++) c[mi][nq][i] = 0.f;

    auto issue = [&](int j) {
        const int kc = 2 * j + gid;
        char* dst = gsm + (j % 3) * STAGE_B;
        const char* a = (kc < 32)
            ? (const char*)(g_Hh[cur] + (size_t)(bm * 32 + kc) * 2048)
            : (const char*)(g_Xh + (size_t)(t * 4 + bm) * 2048);
        const char* b = (const char*)(g_Wh + (size_t)(bn * 33 + kc) * 2048);
#pragma unroll
        for (int it = 0; it < 4; it++) { int e = (it * 128 + gtid) * 16; cp16(dst + e, a + e); }
#pragma unroll
        for (int it = 0; it < 4; it++) { int e = (it * 128 + gtid) * 16; cp16(dst + CHUNK_B + e, b + e); }
        asm volatile("cp.async.commit_group;\n" ::);
    };

    issue(0); issue(1);

    for (int j = 0; j < NCH; j++) {
        if (j < NCH - 1) asm volatile("cp.async.wait_group 1;\n" ::);
        else             asm volatile("cp.async.wait_group 0;\n" ::);
        asm volatile("bar.sync %0, 128;" :: "r"(gid + 1) : "memory");
        if (j + 2 < NCH) issue(j + 2);

        const uint4* sA = (const uint4*)(gsm + (j % 3) * STAGE_B);
        const uint4* sB = (const uint4*)(gsm + (j % 3) * STAGE_B + CHUNK_B);
        uint4 fa[2][2], fb[2][2];
        fa[0][0] = sA[(wm * 2 + 0) * 32 + lane];
        fa[0][1] = sA[(wm * 2 + 1) * 32 + lane];
        fb[0][0] = sB[wn * 64 + lane * 2];
        fb[0][1] = sB[wn * 64 + lane * 2 + 1];
#pragma unroll
        for (int k16 = 0; k16 < 4; k16++) {
            const int cb = k16 & 1, nb = cb ^ 1;
            if (k16 < 3) {
                fa[nb][0] = sA[((k16 + 1) * 4 + wm * 2 + 0) * 32 + lane];
                fa[nb][1] = sA[((k16 + 1) * 4 + wm * 2 + 1) * 32 + lane];
                fb[nb][0] = sB[((k16 + 1) * 2 + wn) * 64 + lane * 2];
                fb[nb][1] = sB[((k16 + 1) * 2 + wn) * 64 + lane * 2 + 1];
            }
            MMA(c[0][0], fa[cb][0], fb[cb][0].x, fb[cb][0].y);
            MMA(c[0][1], fa[cb][0], fb[cb][0].z, fb[cb][0].w);
            MMA(c[0][2], fa[cb][0], fb[cb][1].x, fb[cb][1].y);
            MMA(c[0][3], fa[cb][0], fb[cb][1].z, fb[cb][1].w);
            MMA(c[1][0], fa[cb][1], fb[cb][0].x, fb[cb][0].y);
            MMA(c[1][1], fa[cb][1], fb[cb][0].z, fb[cb][0].w);
            MMA(c[1][2], fa[cb][1], fb[cb][1].x, fb[cb][1].y);
            MMA(c[1][3], fa[cb][1], fb[cb][1].z, fb[cb][1].w);
        }
    }

    // ---------------- combine split-K partials, then epilogue (group 0) ----------------
    __syncthreads();
    float4* xch = (float4*)smem;
    if (gid == 1) {
#pragma unroll
        for (int mi = 0; mi < 2; mi++)
#pragma unroll
            for (int nq = 0; nq < 4; nq++)
                xch[(warp * 32 + lane) * 8 + mi * 4 + nq] = *(const float4*)c[mi][nq];
    }
    __syncthreads();
    if (gid == 0) {
#pragma unroll
        for (int mi = 0; mi < 2; mi++) {
#pragma unroll
            for (int nq = 0; nq < 4; nq++) {
                float4 p = xch[(warp * 32 + lane) * 8 + mi * 4 + nq];
                c[mi][nq][0] += p.x; c[mi][nq][1] += p.y;
                c[mi][nq][2] += p.z; c[mi][nq][3] += p.w;
            }
        }
#pragma unroll
        for (int mi = 0; mi < 2; mi++) {
#pragma unroll
            for (int nq = 0; nq < 4; nq++) {
                const int col = bn * 64 + wn * 32 + nq * 8 + tg * 2;
#pragma unroll
                for (int rhi = 0; rhi < 2; rhi++) {
                    const int row = bm * 64 + wm * 32 + mi * 16 + rhi * 8 + g;
                    const float2 ho = *(const float2*)(g_H[cur] + (size_t)row * R_ + col);
                    float h0 = 0.5f * ho.x + 0.5f * tanhf(c[mi][nq][2 * rhi]);
                    float h1 = 0.5f * ho.y + 0.5f * tanhf(c[mi][nq][2 * rhi + 1]);
                    *(float2*)(g_H[nxt] + (size_t)row * R_ + col) = make_float2(h0, h1);
                    __half2 hh = __floats2half2_rn(h0, h1);
                    const uint32_t off = (uint32_t)(bm * 32 + bn) * 2048u
                        + (uint32_t)((wn * 2 + (nq >> 1)) * 4 + wm * 2 + mi) * 128u
                        + (uint32_t)lane * 4u + (uint32_t)(rhi + 2 * (nq & 1));
                    g_Hh[nxt][off] = *(uint32_t*)&hh;
                }
            }
        }
    }
}

// ---------------- readout ----------------
__global__ void esn_readout(const float* __restrict__ W_out,
                            const float* __restrict__ b_out,
                            float* __restrict__ out)
{
    int b = blockIdx.x, tid = threadIdx.x;
    const float* h = g_H[0] + (size_t)b * R_;
    float acc[O_];
#pragma unroll
    for (int o = 0; o < O_; o++) acc[o] = 0.f;
    for (int r = tid; r < R_; r += 256) {
        float hv = h[r];
#pragma unroll
        for (int o = 0; o < O_; o++) acc[o] += hv * W_out[r * O_ + o];
    }
#pragma unroll
    for (int o = 0; o < O_; o++)
#pragma unroll
        for (int off = 16; off > 0; off >>= 1)
            acc[o] += __shfl_down_sync(0xffffffffu, acc[o], off);
    __shared__ float s[8][O_];
    if ((tid & 31) == 0)
#pragma unroll
        for (int o = 0; o < O_; o++) s[tid >> 5][o] = acc[o];
    __syncthreads();
    if (tid < O_) {
        float v = b_out[tid];
#pragma unroll
        for (int w = 0; w < 8; w++) v += s[w][tid];
        out[b * O_ + tid] = v;
    }
}

extern "C" void kernel_launch(void* const* d_in, const int* in_sizes, int n_in,
                              void* d_out, int out_size)
{
    const float* x     = (const float*)d_in[0];
    const float* W_in  = (const float*)d_in[1];
    const float* W_res = (const float*)d_in[2];
    const float* W_out = (const float*)d_in[3];
    const float* b_out = (const float*)d_in[4];
    float* out = (float*)d_out;

    cudaFuncSetAttribute(esn_step, cudaFuncAttributeMaxDynamicSharedMemorySize, SMEM_BYTES);

    prep_W<<<(1056 * 2048) / 256, 256>>>(W_res, W_in);
    prep_X<<<(B_ * T_ * 32) / 256, 256>>>(x);
    esn_zero<<<512, 256>>>();

    dim3 grid(32, 4);   // bn x bm = 128 CTAs
    for (int t = 0; t < T_; t++)
        esn_step<<<grid, 256, SMEM_BYTES>>>(t);

    esn_readout<<<B_, 256>>>(W_out, b_out, out);
}